// round 10
// baseline (speedup 1.0000x reference)
#include <cuda_runtime.h>
#include <math.h>

#define N_NODES 50000
#define N_EDGES 800000
#define NH 256
#define EH 64
#define HT 128   // NH/2
#define HR 32    // EH/2
#define EPSV 0.01f
#define NSTEPS 10

// ---------------- static scratch (allocation-free) ----------------
__device__ float  g_hsd[(size_t)N_NODES * 64];   // [node*64+j]: j<32 hs, j>=32 hd
__device__ float4 g_cA[N_NODES];                 // coords ping (x,y,z,0)
__device__ float4 g_cB[N_NODES];                 // coords pong
__device__ int    g_cnt[N_NODES];
__device__ int2   g_seg[N_NODES];                // (base, cnt)
__device__ int    g_fill[N_NODES];
__device__ int    g_alloc;
__device__ float4 g_csr[N_EDGES];                // (src_bits, edge_len, 2*step, 0)

__device__ __forceinline__ float leaky(float x) { return x > 0.f ? x : 0.01f * x; }

__device__ __forceinline__ unsigned long long pk(float lo, float hi) {
    unsigned long long r;
    asm("mov.b64 %0, {%1, %2};" : "=l"(r) : "f"(lo), "f"(hi));
    return r;
}
__device__ __forceinline__ void upk(unsigned long long v, float& lo, float& hi) {
    asm("mov.b64 {%0, %1}, %2;" : "=f"(lo), "=f"(hi) : "l"(v));
}
// packed fp32x2 FMA: acc = a*b + acc (exact fp32, 2 MACs/instr)
__device__ __forceinline__ void fma2(unsigned long long& acc, unsigned long long a,
                                     unsigned long long b) {
    asm("fma.rn.f32x2 %0, %1, %2, %0;" : "+l"(acc) : "l"(a), "l"(b));
}

// ---------------------------------------------------------------------------
// Fused node kernel. 128 threads (4 warps -> all 4 SMSPs), 16 nodes/block.
// Every thread owns exactly 1 torsion hidden col (t) for all 16 nodes PLUS
// half a hs/hd column split by node range:
//   t <  64: hsd col t      over nodes 0..7
//   t >= 64: hsd col t-64   over nodes 8..15
// -> uniform 12 FFMA2 per k per thread, no combine step.
// Also performs coord init (g_cA <- cart) and g_cnt zeroing for its 16 nodes.
// ---------------------------------------------------------------------------
__global__ void __launch_bounds__(128) node_kernel(
    const float* __restrict__ node_emb,
    const float* __restrict__ Wt1, const float* __restrict__ bt1,
    const float* __restrict__ Wt2, const float* __restrict__ bt2,
    const float* __restrict__ Wr1,
    const float* __restrict__ cart,
    float* __restrict__ out_tors)
{
    __shared__ __align__(16) float embT[NH * 16];   // [k][n], 16KB
    __shared__ float hact[16][HT + 1];
    __shared__ float tvec[16][3];

    const int t  = threadIdx.x;
    const int nb = blockIdx.x * 16;

    // fold in coord init + histogram zeroing for this block's 16 nodes
    if (t < 16) {
        const int n = nb + t;
        g_cA[n] = make_float4(cart[n * 3 + 0], cart[n * 3 + 1], cart[n * 3 + 2], 0.f);
        g_cnt[n] = 0;
    }

    // stage emb rows transposed: embT[k*16 + n]
    const float* src = node_emb + (size_t)nb * NH;
    for (int i = t; i < 16 * NH; i += 128)
        embT[(i & (NH - 1)) * 16 + (i >> 8)] = src[i];
    __syncthreads();

    // torsion accumulators: col t, 16 nodes (8 f32x2)
    unsigned long long accT[8];
    {
        const float b0 = bt1[t];
        #pragma unroll
        for (int m = 0; m < 8; m++) accT[m] = pk(b0, b0);
    }
    // hsd accumulators: 8 nodes (4 f32x2)
    unsigned long long accH[4];
    #pragma unroll
    for (int m = 0; m < 4; m++) accH[m] = 0ull;

    const int  c64  = t & 63;
    const int  hoff = (t < 64) ? 0 : 8;     // node sub-range for hsd
    const float* wpT = Wt1 + t;             // Wt1[k*HT + t]
    const float* wpH = (c64 < HR) ? (Wr1 + EH * HR + c64)            // Ws col
                                  : (Wr1 + (EH + NH) * HR + (c64 - HR)); // Wd col

    #pragma unroll 2
    for (int k = 0; k < NH; k++) {
        const float wT = wpT[k * HT];
        const float wH = wpH[k * HR];
        const unsigned long long wwT = pk(wT, wT);
        const unsigned long long wwH = pk(wH, wH);
        const ulonglong2* r = (const ulonglong2*)(embT + k * 16);
        const ulonglong2 p0 = r[0], p1 = r[1], p2 = r[2], p3 = r[3];
        fma2(accT[0], p0.x, wwT); fma2(accT[1], p0.y, wwT);
        fma2(accT[2], p1.x, wwT); fma2(accT[3], p1.y, wwT);
        fma2(accT[4], p2.x, wwT); fma2(accT[5], p2.y, wwT);
        fma2(accT[6], p3.x, wwT); fma2(accT[7], p3.y, wwT);
        const ulonglong2* rh = (const ulonglong2*)(embT + k * 16 + hoff);
        const ulonglong2 q0 = rh[0], q1 = rh[1];
        fma2(accH[0], q0.x, wwH); fma2(accH[1], q0.y, wwH);
        fma2(accH[2], q1.x, wwH); fma2(accH[3], q1.y, wwH);
    }

    // torsion epilogue: hact[n][t]
    #pragma unroll
    for (int m = 0; m < 8; m++) {
        float lo, hi;
        upk(accT[m], lo, hi);
        hact[2 * m][t]     = leaky(lo);
        hact[2 * m + 1][t] = leaky(hi);
    }
    // hsd epilogue: 8 nodes, col c64
    {
        const int nbase = nb + hoff;
        #pragma unroll
        for (int m = 0; m < 4; m++) {
            float lo, hi;
            upk(accH[m], lo, hi);
            g_hsd[(size_t)(nbase + 2 * m) * 64 + c64]     = lo;
            g_hsd[(size_t)(nbase + 2 * m + 1) * 64 + c64] = hi;
        }
    }
    __syncthreads();

    // layer 2: 16 nodes x 3 components
    if (t < 48) {
        const int n = t / 3, c = t % 3;
        float s = bt2[c];
        #pragma unroll 8
        for (int j = 0; j < HT; j++) s += hact[n][j] * Wt2[j * 3 + c];
        tvec[n][c] = s;
    }
    __syncthreads();

    if (t < 16) {
        const float t0 = tvec[t][0], t1 = tvec[t][1], t2 = tvec[t][2];
        const float rho = sqrtf(t0 * t0 + t1 * t1 + t2 * t2);
        const float inv = 1.f / rho;
        const float n0 = t0 * inv, n1 = t1 * inv, n2 = t2 * inv;
        const float half_pi = 1.57079632679489662f;
        const float theta = (fabsf(n0) > fabsf(n1)) ? atan2f(n1, n0)
                                                    : (half_pi - atan2f(n0, n1));
        const float cz  = fminf(fmaxf(n2, -1.f + EPSV), 1.f - EPSV);
        const float phi = acosf(cz);
        const int node = nb + t;
        out_tors[node * 3 + 0] = rho;
        out_tors[node * 3 + 1] = phi;
        out_tors[node * 3 + 2] = theta;
    }
}

// ---------------------------------------------------------------------------
// histogram of dest degrees (g_cnt zeroed by node_kernel); also zero g_alloc
// ---------------------------------------------------------------------------
__global__ void __launch_bounds__(256) hist_kernel(const int* __restrict__ ei)
{
    const int e = blockIdx.x * blockDim.x + threadIdx.x;
    if (e == 0) g_alloc = 0;
    if (e < N_EDGES) atomicAdd(&g_cnt[ei[N_EDGES + e]], 1);
}

// ---------------------------------------------------------------------------
// alloc: disjoint CSR segment bases (order irrelevant). Warp scan + block
// aggregation + one global atomic per block.
// ---------------------------------------------------------------------------
__global__ void __launch_bounds__(256) alloc_kernel()
{
    __shared__ int wsum[8];
    __shared__ int sbase;
    const int t    = threadIdx.x;
    const int lane = t & 31;
    const int wrp  = t >> 5;
    const int n    = blockIdx.x * 256 + t;
    const int c    = (n < N_NODES) ? g_cnt[n] : 0;

    int pre = c;
    #pragma unroll
    for (int o = 1; o < 32; o <<= 1) {
        const int v = __shfl_up_sync(0xFFFFFFFFu, pre, o);
        if (lane >= o) pre += v;
    }
    if (lane == 31) wsum[wrp] = pre;
    __syncthreads();
    if (t == 0) {
        int s = 0;
        #pragma unroll
        for (int w = 0; w < 8; w++) { const int tmp = wsum[w]; wsum[w] = s; s += tmp; }
        sbase = atomicAdd(&g_alloc, s);
    }
    __syncthreads();
    if (n < N_NODES) {
        const int b = sbase + wsum[wrp] + pre - c;
        g_seg[n]  = make_int2(b, c);
        g_fill[n] = b;
    }
}

// ---------------------------------------------------------------------------
// Edge MLP + CSR scatter. 128 edges/block, 256 threads (8 warps x 16 edges).
// Writes one float4 CSR record per edge: (src_bits, edge_len, 2*step, 0).
// ---------------------------------------------------------------------------
#define E_PAD 132
__global__ void __launch_bounds__(256) edge_kernel(
    const float* __restrict__ edge_emb,
    const float* __restrict__ Wr1, const float* __restrict__ br1,
    const float* __restrict__ Wr2, const float* __restrict__ br2,
    const int* __restrict__ ei)
{
    __shared__ __align__(16) float Wes[EH * HR];
    __shared__ __align__(16) float eT[EH * E_PAD];
    __shared__ float br1s[HR], w2a[HR], w2b[HR];

    const int t = threadIdx.x;
    for (int i = t; i < EH * HR; i += 256) Wes[i] = Wr1[i];
    if (t < HR) { br1s[t] = br1[t]; w2a[t] = Wr2[t * 2]; w2b[t] = Wr2[t * 2 + 1]; }

    const int e_base = blockIdx.x * 128;
    const float* es = edge_emb + (size_t)e_base * EH;
    for (int i = t; i < 128 * EH; i += 256)
        eT[(i & 63) * E_PAD + (i >> 6)] = es[i];
    __syncthreads();

    const int j  = t & 31;
    const int e0 = (t >> 5) * 16;

    unsigned long long acc[8];
    #pragma unroll
    for (int m = 0; m < 8; m++) acc[m] = 0ull;

    #pragma unroll 4
    for (int k = 0; k < EH; k++) {
        const float w = Wes[k * HR + j];
        const unsigned long long ww = pk(w, w);
        const ulonglong2* r = (const ulonglong2*)(eT + k * E_PAD + e0);
        const ulonglong2 p0 = r[0], p1 = r[1], p2 = r[2], p3 = r[3];
        fma2(acc[0], p0.x, ww); fma2(acc[1], p0.y, ww);
        fma2(acc[2], p1.x, ww); fma2(acc[3], p1.y, ww);
        fma2(acc[4], p2.x, ww); fma2(acc[5], p2.y, ww);
        fma2(acc[6], p3.x, ww); fma2(acc[7], p3.y, ww);
    }
    float av[16];
    #pragma unroll
    for (int m = 0; m < 8; m++) upk(acc[m], av[2 * m], av[2 * m + 1]);

    const float bj = br1s[j], wa = w2a[j], wb = w2b[j];
    float my0 = 0.f, my1 = 0.f;
    int my_s = 0, my_d = 0;

    #pragma unroll
    for (int idx = 0; idx < 16; idx++) {
        const int e = e_base + e0 + idx;
        const int s = ei[e];
        const int d = ei[N_EDGES + e];
        float hh = av[idx] + bj + g_hsd[(size_t)s * 64 + j]
                 + g_hsd[(size_t)d * 64 + 32 + j];
        hh = leaky(hh);
        float r0 = hh * wa, r1 = hh * wb;
        #pragma unroll
        for (int o = 16; o; o >>= 1) {
            r0 += __shfl_xor_sync(0xFFFFFFFFu, r0, o);
            r1 += __shfl_xor_sync(0xFFFFFFFFu, r1, o);
        }
        if (j == idx) { my0 = r0; my1 = r1; my_s = s; my_d = d; }
    }

    if (j < 16) {
        const float o0 = my0 + br2[0] + 1.0f;
        const float el = (o0 > 20.f) ? o0 : log1pf(expf(o0));
        const float o1 = my1 + br2[1] - 2.0f;
        const float st = 1.f / (1.f + expf(-o1));
        const int pos = atomicAdd(&g_fill[my_d], 1);
        g_csr[pos] = make_float4(__int_as_float(my_s), el, 2.f * st, 0.f);
    }
}

// ---------------------------------------------------------------------------
// Refine step: per node gather from CSR (no atomics). 4 lanes/node.
// One LDG.128 per CSR record + one LDG.128 coord gather. LAST writes packed
// float3 directly into d_out.
// ---------------------------------------------------------------------------
template <bool LAST>
__global__ void __launch_bounds__(256) refine_kernel(
    const float4* __restrict__ cin, float4* __restrict__ cout,
    float* __restrict__ out3)
{
    const int g = blockIdx.x * 256 + threadIdx.x;
    const int n = g >> 2, l = g & 3;
    if (n >= N_NODES) return;
    const int2 seg = g_seg[n];
    const float4 c = cin[n];
    float fx = 0.f, fy = 0.f, fz = 0.f;
    const int end = seg.x + seg.y;
    #pragma unroll 2
    for (int i = seg.x + l; i < end; i += 4) {
        const float4 e = __ldg(&g_csr[i]);
        const int s = __float_as_int(e.x);
        const float4 cs = __ldg(&cin[s]);
        const float ddx = c.x - cs.x;
        const float ddy = c.y - cs.y;
        const float ddz = c.z - cs.z;
        const float dist = sqrtf(ddx * ddx + ddy * ddy + ddz * ddz);
        const float f = e.z * (e.y - dist) / (dist + EPSV);
        fx += f * ddx; fy += f * ddy; fz += f * ddz;
    }
    fx += __shfl_xor_sync(0xFFFFFFFFu, fx, 1);
    fy += __shfl_xor_sync(0xFFFFFFFFu, fy, 1);
    fz += __shfl_xor_sync(0xFFFFFFFFu, fz, 1);
    fx += __shfl_xor_sync(0xFFFFFFFFu, fx, 2);
    fy += __shfl_xor_sync(0xFFFFFFFFu, fy, 2);
    fz += __shfl_xor_sync(0xFFFFFFFFu, fz, 2);
    if (l == 0) {
        const float an = sqrtf(fx * fx + fy * fy + fz * fz) + EPSV;
        const float sc = fminf(an, 0.5f) / an;
        if (LAST) {
            out3[n * 3 + 0] = c.x + fx * sc;
            out3[n * 3 + 1] = c.y + fy * sc;
            out3[n * 3 + 2] = c.z + fz * sc;
        } else {
            cout[n] = make_float4(c.x + fx * sc, c.y + fy * sc, c.z + fz * sc, 0.f);
        }
    }
}

// ---------------------------------------------------------------------------
extern "C" void kernel_launch(void* const* d_in, const int* in_sizes, int n_in,
                              void* d_out, int out_size)
{
    const float* node_emb = (const float*)d_in[0];
    const float* edge_emb = (const float*)d_in[1];
    const float* cart     = (const float*)d_in[2];
    const float* Wt1      = (const float*)d_in[3];
    const float* bt1      = (const float*)d_in[4];
    const float* Wt2      = (const float*)d_in[5];
    const float* bt2      = (const float*)d_in[6];
    const float* Wr1      = (const float*)d_in[7];
    const float* br1      = (const float*)d_in[8];
    const float* Wr2      = (const float*)d_in[9];
    const float* br2      = (const float*)d_in[10];
    const int*   ei       = (const int*)d_in[11];

    float* out_coords = (float*)d_out;
    float* out_tors   = (float*)d_out + N_NODES * 3;

    float4 *cA = nullptr, *cB = nullptr;
    cudaGetSymbolAddress((void**)&cA, g_cA);
    cudaGetSymbolAddress((void**)&cB, g_cB);

    // 1: fused node MLPs + coord init + cnt zero
    node_kernel<<<N_NODES / 16, 128>>>(node_emb, Wt1, bt1, Wt2, bt2, Wr1,
                                       cart, out_tors);
    // 2-3: histogram (also zeroes g_alloc) + CSR allocation
    hist_kernel<<<(N_EDGES + 255) / 256, 256>>>(ei);
    alloc_kernel<<<(N_NODES + 255) / 256, 256>>>();

    // 4: edge MLP -> CSR records  [ncu capture target]
    edge_kernel<<<N_EDGES / 128, 256>>>(edge_emb, Wr1, br1, Wr2, br2, ei);

    // 5-14: refinement (ping-pong float4; last iter writes packed to d_out)
    const int rblocks = (N_NODES * 4 + 255) / 256;
    for (int it = 0; it < NSTEPS; it++) {
        const float4* cin = (it & 1) ? cB : cA;
        float4*      cout = (it & 1) ? cA : cB;
        if (it == NSTEPS - 1)
            refine_kernel<true><<<rblocks, 256>>>(cin, cout, out_coords);
        else
            refine_kernel<false><<<rblocks, 256>>>(cin, cout, nullptr);
    }
}

// round 12
// speedup vs baseline: 1.1893x; 1.1893x over previous
#include <cuda_runtime.h>
#include <math.h>

#define N_NODES 50000
#define N_EDGES 800000
#define NH 256
#define EH 64
#define HT 128   // NH/2
#define HR 32    // EH/2
#define EPSV 0.01f
#define NSTEPS 10

// ---------------- static scratch (allocation-free) ----------------
__device__ float  g_hsd[(size_t)N_NODES * 64];   // [node*64+j]: j<32 hs, j>=32 hd
__device__ float4 g_cA[N_NODES];                 // coords ping (x,y,z,0)
__device__ float4 g_cB[N_NODES];                 // coords pong
__device__ int    g_cnt[N_NODES];
__device__ int2   g_seg[N_NODES];                // (base, cnt)
__device__ int    g_fill[N_NODES];
__device__ int    g_alloc;
__device__ float4 g_csr[N_EDGES];                // (src_bits, edge_len, 2*step, 0)

__device__ __forceinline__ float leaky(float x) { return x > 0.f ? x : 0.01f * x; }

__device__ __forceinline__ unsigned long long pk(float lo, float hi) {
    unsigned long long r;
    asm("mov.b64 %0, {%1, %2};" : "=l"(r) : "f"(lo), "f"(hi));
    return r;
}
__device__ __forceinline__ void upk(unsigned long long v, float& lo, float& hi) {
    asm("mov.b64 {%0, %1}, %2;" : "=f"(lo), "=f"(hi) : "l"(v));
}
// packed fp32x2 FMA: acc = a*b + acc (exact fp32, 2 MACs/instr)
__device__ __forceinline__ void fma2(unsigned long long& acc, unsigned long long a,
                                     unsigned long long b) {
    asm("fma.rn.f32x2 %0, %1, %2, %0;" : "+l"(acc) : "l"(a), "l"(b));
}

// ---------------------------------------------------------------------------
// Fused node kernel. 96 threads, 16 nodes/block (R4-measured structure).
// t <  64: torsion hidden cols t and t+64, all 16 nodes (16 FFMA2/k)
// t >= 64: hs col (t-64) and hd col (t-64), all 16 nodes (16 FFMA2/k)
// NEW vs R4: weight loads software-pipelined in chunks of 8 k (16 LDGs
// front-batched per body) to cover ~234cyc L2 latency that limited issue=38%.
// Also folds coord init + g_cnt zeroing.
// ---------------------------------------------------------------------------
__global__ void __launch_bounds__(96) node_kernel(
    const float* __restrict__ node_emb,
    const float* __restrict__ Wt1, const float* __restrict__ bt1,
    const float* __restrict__ Wt2, const float* __restrict__ bt2,
    const float* __restrict__ Wr1,
    const float* __restrict__ cart,
    float* __restrict__ out_tors)
{
    __shared__ __align__(16) float embT[NH * 16];   // [k][n], 16KB
    __shared__ float hact[16][HT + 1];
    __shared__ float tvec[16][3];

    const int t  = threadIdx.x;
    const int nb = blockIdx.x * 16;

    if (t < 16) {
        const int n = nb + t;
        g_cA[n] = make_float4(cart[n * 3 + 0], cart[n * 3 + 1], cart[n * 3 + 2], 0.f);
        g_cnt[n] = 0;
    }

    const float* src = node_emb + (size_t)nb * NH;
    for (int i = t; i < 16 * NH; i += 96)
        embT[(i & (NH - 1)) * 16 + (i >> 8)] = src[i];
    __syncthreads();

    unsigned long long accA[8], accB[8];
    const float* wpA;
    const float* wpB;
    int strideW;
    if (t < 64) {
        const float b0 = bt1[t], b1 = bt1[t + 64];
        #pragma unroll
        for (int m = 0; m < 8; m++) { accA[m] = pk(b0, b0); accB[m] = pk(b1, b1); }
        wpA = Wt1 + t;
        wpB = Wt1 + t + 64;
        strideW = HT;
    } else {
        #pragma unroll
        for (int m = 0; m < 8; m++) { accA[m] = 0ull; accB[m] = 0ull; }
        const int c = t - 64;
        wpA = Wr1 + EH * HR + c;          // Ws col c
        wpB = Wr1 + (EH + NH) * HR + c;   // Wd col c
        strideW = HR;
    }

    // software-pipelined mainloop: 16 weight LDGs batched per 8-k body
    #pragma unroll 1
    for (int kk = 0; kk < NH; kk += 8) {
        float wa[8], wb[8];
        #pragma unroll
        for (int u = 0; u < 8; u++) {
            wa[u] = wpA[(kk + u) * strideW];
            wb[u] = wpB[(kk + u) * strideW];
        }
        #pragma unroll
        for (int u = 0; u < 8; u++) {
            const unsigned long long wwA = pk(wa[u], wa[u]);
            const unsigned long long wwB = pk(wb[u], wb[u]);
            const ulonglong2* r = (const ulonglong2*)(embT + (kk + u) * 16);
            const ulonglong2 p0 = r[0], p1 = r[1], p2 = r[2], p3 = r[3];
            fma2(accA[0], p0.x, wwA); fma2(accA[1], p0.y, wwA);
            fma2(accA[2], p1.x, wwA); fma2(accA[3], p1.y, wwA);
            fma2(accA[4], p2.x, wwA); fma2(accA[5], p2.y, wwA);
            fma2(accA[6], p3.x, wwA); fma2(accA[7], p3.y, wwA);
            fma2(accB[0], p0.x, wwB); fma2(accB[1], p0.y, wwB);
            fma2(accB[2], p1.x, wwB); fma2(accB[3], p1.y, wwB);
            fma2(accB[4], p2.x, wwB); fma2(accB[5], p2.y, wwB);
            fma2(accB[6], p3.x, wwB); fma2(accB[7], p3.y, wwB);
        }
    }

    if (t < 64) {
        #pragma unroll
        for (int m = 0; m < 8; m++) {
            float lo, hi;
            upk(accA[m], lo, hi);
            hact[2 * m][t] = leaky(lo); hact[2 * m + 1][t] = leaky(hi);
            upk(accB[m], lo, hi);
            hact[2 * m][t + 64] = leaky(lo); hact[2 * m + 1][t + 64] = leaky(hi);
        }
    } else {
        const int c = t - 64;
        #pragma unroll
        for (int m = 0; m < 8; m++) {
            float lo, hi;
            upk(accA[m], lo, hi);
            g_hsd[(size_t)(nb + 2 * m) * 64 + c]     = lo;
            g_hsd[(size_t)(nb + 2 * m + 1) * 64 + c] = hi;
            upk(accB[m], lo, hi);
            g_hsd[(size_t)(nb + 2 * m) * 64 + 32 + c]     = lo;
            g_hsd[(size_t)(nb + 2 * m + 1) * 64 + 32 + c] = hi;
        }
    }
    __syncthreads();

    if (t < 48) {
        const int n = t / 3, c = t % 3;
        float s = bt2[c];
        #pragma unroll 8
        for (int j = 0; j < HT; j++) s += hact[n][j] * Wt2[j * 3 + c];
        tvec[n][c] = s;
    }
    __syncthreads();

    if (t < 16) {
        const float t0 = tvec[t][0], t1 = tvec[t][1], t2 = tvec[t][2];
        const float rho = sqrtf(t0 * t0 + t1 * t1 + t2 * t2);
        const float inv = 1.f / rho;
        const float n0 = t0 * inv, n1 = t1 * inv, n2 = t2 * inv;
        const float half_pi = 1.57079632679489662f;
        const float theta = (fabsf(n0) > fabsf(n1)) ? atan2f(n1, n0)
                                                    : (half_pi - atan2f(n0, n1));
        const float cz  = fminf(fmaxf(n2, -1.f + EPSV), 1.f - EPSV);
        const float phi = acosf(cz);
        const int node = nb + t;
        out_tors[node * 3 + 0] = rho;
        out_tors[node * 3 + 1] = phi;
        out_tors[node * 3 + 2] = theta;
    }
}

// ---------------------------------------------------------------------------
__global__ void __launch_bounds__(256) hist_kernel(const int* __restrict__ ei)
{
    const int e = blockIdx.x * blockDim.x + threadIdx.x;
    if (e == 0) g_alloc = 0;
    if (e < N_EDGES) atomicAdd(&g_cnt[ei[N_EDGES + e]], 1);
}

// ---------------------------------------------------------------------------
__global__ void __launch_bounds__(256) alloc_kernel()
{
    __shared__ int wsum[8];
    __shared__ int sbase;
    const int t    = threadIdx.x;
    const int lane = t & 31;
    const int wrp  = t >> 5;
    const int n    = blockIdx.x * 256 + t;
    const int c    = (n < N_NODES) ? g_cnt[n] : 0;

    int pre = c;
    #pragma unroll
    for (int o = 1; o < 32; o <<= 1) {
        const int v = __shfl_up_sync(0xFFFFFFFFu, pre, o);
        if (lane >= o) pre += v;
    }
    if (lane == 31) wsum[wrp] = pre;
    __syncthreads();
    if (t == 0) {
        int s = 0;
        #pragma unroll
        for (int w = 0; w < 8; w++) { const int tmp = wsum[w]; wsum[w] = s; s += tmp; }
        sbase = atomicAdd(&g_alloc, s);
    }
    __syncthreads();
    if (n < N_NODES) {
        const int b = sbase + wsum[wrp] + pre - c;
        g_seg[n]  = make_int2(b, c);
        g_fill[n] = b;
    }
}

// ---------------------------------------------------------------------------
// Edge MLP + CSR scatter. 128 edges/block, 256 threads (8 warps x 16 edges).
// vs R10 (MIO-bound, L1=90.1%):
//  - eT per-warp [k][16] rows with row stride 20 floats (80B: 16B-aligned for
//    LDS.128 broadcast reads; 20k mod 32 spans 8 banks -> 4-way staging STS,
//    same as R10, NOT the 16-way a stride-16 row would give).
//  - epilogue: smem transpose reduce in the warp's own eT region replaces the
//    160-shfl/warp reduction; packed f32x2 second-layer weights.
// ---------------------------------------------------------------------------
#define KROW 20                    // floats per k row (80B, 16B-aligned)
#define EG_STRIDE (EH * KROW)      // 1280 floats per warp group
__global__ void __launch_bounds__(256) edge_kernel(
    const float* __restrict__ edge_emb,
    const float* __restrict__ Wr1, const float* __restrict__ br1,
    const float* __restrict__ Wr2, const float* __restrict__ br2,
    const int* __restrict__ ei)
{
    __shared__ __align__(16) float Wes[EH * HR];          // 8KB
    __shared__ __align__(16) float eT[8 * EG_STRIDE];     // 40KB
    __shared__ unsigned long long w2pk[HR];               // packed (wa,wb)
    __shared__ float br1s[HR];

    const int t = threadIdx.x;
    for (int i = t; i < EH * HR; i += 256) Wes[i] = Wr1[i];
    if (t < HR) { br1s[t] = br1[t]; w2pk[t] = pk(Wr2[t * 2], Wr2[t * 2 + 1]); }

    const int e_base = blockIdx.x * 128;
    const float* es = edge_emb + (size_t)e_base * EH;
    // stage: es[e][k] -> eT[(e>>4)*EG_STRIDE + k*KROW + (e&15)]
    for (int i = t; i < 128 * EH; i += 256) {
        const int e = i >> 6, k = i & 63;
        eT[(e >> 4) * EG_STRIDE + k * KROW + (e & 15)] = es[i];
    }
    __syncthreads();

    const int j = t & 31;
    const int w = t >> 5;
    float* myT = eT + w * EG_STRIDE;

    unsigned long long acc[8];
    #pragma unroll
    for (int m = 0; m < 8; m++) acc[m] = 0ull;

    #pragma unroll 4
    for (int k = 0; k < EH; k++) {
        const float wv = Wes[k * HR + j];
        const unsigned long long ww = pk(wv, wv);
        const ulonglong2* r = (const ulonglong2*)(myT + k * KROW);
        const ulonglong2 p0 = r[0], p1 = r[1], p2 = r[2], p3 = r[3];
        fma2(acc[0], p0.x, ww); fma2(acc[1], p0.y, ww);
        fma2(acc[2], p1.x, ww); fma2(acc[3], p1.y, ww);
        fma2(acc[4], p2.x, ww); fma2(acc[5], p2.y, ww);
        fma2(acc[6], p3.x, ww); fma2(acc[7], p3.y, ww);
    }
    float av[16];
    #pragma unroll
    for (int m = 0; m < 8; m++) upk(acc[m], av[2 * m], av[2 * m + 1]);

    // epilogue: hh into the warp's own eT region (done reading it), 32x17 pad
    const float bj = br1s[j];
    #pragma unroll
    for (int idx = 0; idx < 16; idx++) {
        const int e = e_base + w * 16 + idx;
        const int s = ei[e];
        const int d = ei[N_EDGES + e];
        const float hh = leaky(av[idx] + bj + g_hsd[(size_t)s * 64 + j]
                               + g_hsd[(size_t)d * 64 + 32 + j]);
        myT[j * 17 + idx] = hh;
    }
    __syncwarp();

    if (j < 16) {
        unsigned long long acc01 = 0ull;
        #pragma unroll 8
        for (int jj = 0; jj < 32; jj++) {
            const float h = myT[jj * 17 + j];
            fma2(acc01, pk(h, h), w2pk[jj]);
        }
        float r0, r1;
        upk(acc01, r0, r1);
        const int e = e_base + w * 16 + j;
        const int my_s = ei[e];
        const int my_d = ei[N_EDGES + e];
        const float o0 = r0 + br2[0] + 1.0f;
        const float el = (o0 > 20.f) ? o0 : log1pf(expf(o0));
        const float o1 = r1 + br2[1] - 2.0f;
        const float st = 1.f / (1.f + expf(-o1));
        const int pos = atomicAdd(&g_fill[my_d], 1);
        g_csr[pos] = make_float4(__int_as_float(my_s), el, 2.f * st, 0.f);
    }
}

// ---------------------------------------------------------------------------
// Refine step (unchanged; no measurement data yet)
// ---------------------------------------------------------------------------
template <bool LAST>
__global__ void __launch_bounds__(256) refine_kernel(
    const float4* __restrict__ cin, float4* __restrict__ cout,
    float* __restrict__ out3)
{
    const int g = blockIdx.x * 256 + threadIdx.x;
    const int n = g >> 2, l = g & 3;
    if (n >= N_NODES) return;
    const int2 seg = g_seg[n];
    const float4 c = cin[n];
    float fx = 0.f, fy = 0.f, fz = 0.f;
    const int end = seg.x + seg.y;
    #pragma unroll 2
    for (int i = seg.x + l; i < end; i += 4) {
        const float4 e = __ldg(&g_csr[i]);
        const int s = __float_as_int(e.x);
        const float4 cs = __ldg(&cin[s]);
        const float ddx = c.x - cs.x;
        const float ddy = c.y - cs.y;
        const float ddz = c.z - cs.z;
        const float dist = sqrtf(ddx * ddx + ddy * ddy + ddz * ddz);
        const float f = e.z * (e.y - dist) / (dist + EPSV);
        fx += f * ddx; fy += f * ddy; fz += f * ddz;
    }
    fx += __shfl_xor_sync(0xFFFFFFFFu, fx, 1);
    fy += __shfl_xor_sync(0xFFFFFFFFu, fy, 1);
    fz += __shfl_xor_sync(0xFFFFFFFFu, fz, 1);
    fx += __shfl_xor_sync(0xFFFFFFFFu, fx, 2);
    fy += __shfl_xor_sync(0xFFFFFFFFu, fy, 2);
    fz += __shfl_xor_sync(0xFFFFFFFFu, fz, 2);
    if (l == 0) {
        const float an = sqrtf(fx * fx + fy * fy + fz * fz) + EPSV;
        const float sc = fminf(an, 0.5f) / an;
        if (LAST) {
            out3[n * 3 + 0] = c.x + fx * sc;
            out3[n * 3 + 1] = c.y + fy * sc;
            out3[n * 3 + 2] = c.z + fz * sc;
        } else {
            cout[n] = make_float4(c.x + fx * sc, c.y + fy * sc, c.z + fz * sc, 0.f);
        }
    }
}

// ---------------------------------------------------------------------------
extern "C" void kernel_launch(void* const* d_in, const int* in_sizes, int n_in,
                              void* d_out, int out_size)
{
    const float* node_emb = (const float*)d_in[0];
    const float* edge_emb = (const float*)d_in[1];
    const float* cart     = (const float*)d_in[2];
    const float* Wt1      = (const float*)d_in[3];
    const float* bt1      = (const float*)d_in[4];
    const float* Wt2      = (const float*)d_in[5];
    const float* bt2      = (const float*)d_in[6];
    const float* Wr1      = (const float*)d_in[7];
    const float* br1      = (const float*)d_in[8];
    const float* Wr2      = (const float*)d_in[9];
    const float* br2      = (const float*)d_in[10];
    const int*   ei       = (const int*)d_in[11];

    float* out_coords = (float*)d_out;
    float* out_tors   = (float*)d_out + N_NODES * 3;

    float4 *cA = nullptr, *cB = nullptr;
    cudaGetSymbolAddress((void**)&cA, g_cA);
    cudaGetSymbolAddress((void**)&cB, g_cB);

    // 1: fused node MLPs + coord init + cnt zero
    node_kernel<<<N_NODES / 16, 96>>>(node_emb, Wt1, bt1, Wt2, bt2, Wr1,
                                      cart, out_tors);
    // 2-3: histogram (also zeroes g_alloc) + CSR allocation
    hist_kernel<<<(N_EDGES + 255) / 256, 256>>>(ei);
    alloc_kernel<<<(N_NODES + 255) / 256, 256>>>();

    // 4: edge MLP -> CSR records  [ncu capture target: A/B vs R10's 180.9us]
    edge_kernel<<<N_EDGES / 128, 256>>>(edge_emb, Wr1, br1, Wr2, br2, ei);

    // 5-14: refinement (ping-pong float4; last iter writes packed to d_out)
    const int rblocks = (N_NODES * 4 + 255) / 256;
    for (int it = 0; it < NSTEPS; it++) {
        const float4* cin = (it & 1) ? cB : cA;
        float4*      cout = (it & 1) ? cA : cB;
        if (it == NSTEPS - 1)
            refine_kernel<true><<<rblocks, 256>>>(cin, cout, out_coords);
        else
            refine_kernel<false><<<rblocks, 256>>>(cin, cout, nullptr);
    }
}